// round 15
// baseline (speedup 1.0000x reference)
#include <cuda_runtime.h>
#include <cuda_bf16.h>

#define BSZ    640
#define INCH   2048
#define OUTCH  696
#define NS     174
#define CHROWS 320
#define WROWS  704              // OUTCH padded to 64
#define KSPLIT 4
#define KSLICE (INCH / KSPLIT)  // 512

// ---------------- scratch ----------------
__device__ __nv_bfloat16 g_xhi[BSZ * INCH];
__device__ __nv_bfloat16 g_xlo[BSZ * INCH];
__device__ __nv_bfloat16 g_whi[WROWS * INCH];
__device__ __nv_bfloat16 g_wlo[WROWS * INCH];
__device__ float g_hpart[KSPLIT][BSZ * OUTCH];
__device__ float g_h   [BSZ * OUTCH];
__device__ float g_hmul[BSZ * OUTCH];
__device__ float g_q   [OUTCH * BSZ];
__device__ float g_k   [OUTCH * BSZ];
__device__ float g_v   [OUTCH * BSZ];
__device__ float g_o   [BSZ * OUTCH];   // NOW [l][c] — epi reads coalesced
__device__ float g_sum [2 * OUTCH];     // after reduce: BN affine scale A
__device__ float g_sq  [2 * OUTCH];     // after reduce: BN affine shift B

#define LOG2E 1.4426950408889634f

__device__ __forceinline__ float ex2(float x) {
    float y;
    asm("ex2.approx.ftz.f32 %0, %1;" : "=f"(y) : "f"(x));
    return y;
}

// exp2 entirely on FMA/ALU pipes (numerically validated in round 11)
__device__ __forceinline__ float exp2_poly(float x) {
    float t = x + 12582912.0f;            // 1.5*2^23
    int   e = __float_as_int(t) << 23;
    float n = t - 12582912.0f;
    float f = x - n;                      // [-0.5, 0.5]
    float p = 1.3333558146e-3f;
    p = fmaf(p, f, 9.6181291076e-3f);
    p = fmaf(p, f, 5.5504108665e-2f);
    p = fmaf(p, f, 2.4022650696e-1f);
    p = fmaf(p, f, 6.9314718056e-1f);
    p = fmaf(p, f, 1.0f);
    return __int_as_float(__float_as_int(p) + e);
}

__device__ __forceinline__ unsigned smem_to_u32(const void* p) {
    unsigned a;
    asm("{ .reg .u64 t; cvta.to.shared.u64 t, %1; cvt.u32.u64 %0, t; }" : "=r"(a) : "l"(p));
    return a;
}

#define CP_ASYNC16(dst_u32, src_ptr) \
    asm volatile("cp.async.cg.shared.global [%0], [%1], 16;" :: "r"(dst_u32), "l"(src_ptr) : "memory")
#define CP_COMMIT() asm volatile("cp.async.commit_group;" ::: "memory")
#define CP_WAIT0()  asm volatile("cp.async.wait_group 0;" ::: "memory")

#define LDSM_X4(r0, r1, r2, r3, addr) \
    asm volatile("ldmatrix.sync.aligned.m8n8.x4.shared.b16 {%0,%1,%2,%3}, [%4];" \
        : "=r"(r0), "=r"(r1), "=r"(r2), "=r"(r3) : "r"(addr))

// ---------------- kernel 0: fp32 -> bf16 hi/lo split ----------------
__global__ __launch_bounds__(256) void prep_kernel(const float* __restrict__ x,
                                                   const float* __restrict__ w) {
    const int gid = blockIdx.x * 256 + threadIdx.x;
    const int XQ = BSZ * INCH / 4;
    const int WQ = WROWS * INCH / 4;
    float4 v;
    uint2 *hid, *lod;
    if (gid < XQ) {
        v = ((const float4*)x)[gid];
        hid = (uint2*)g_xhi + gid; lod = (uint2*)g_xlo + gid;
    } else {
        int q = gid - XQ;
        if (q >= WQ) return;
        v = (q < OUTCH * (INCH / 4)) ? ((const float4*)w)[q] : make_float4(0.f, 0.f, 0.f, 0.f);
        hid = (uint2*)g_whi + q; lod = (uint2*)g_wlo + q;
    }
    float fv[4] = {v.x, v.y, v.z, v.w};
    unsigned short hs[4], ls[4];
    #pragma unroll
    for (int i = 0; i < 4; i++) {
        __nv_bfloat16 h = __float2bfloat16(fv[i]);
        __nv_bfloat16 l = __float2bfloat16(fv[i] - __bfloat162float(h));
        hs[i] = __bfloat16_as_ushort(h);
        ls[i] = __bfloat16_as_ushort(l);
    }
    uint2 H, L;
    H.x = ((unsigned)hs[1] << 16) | hs[0]; H.y = ((unsigned)hs[3] << 16) | hs[2];
    L.x = ((unsigned)ls[1] << 16) | ls[0]; L.y = ((unsigned)ls[3] << 16) | ls[2];
    *hid = H; *lod = L;
}

// ---------------- mma.sync m16n8k16 bf16 ----------------
__device__ __forceinline__ void mma16816(float* c, const unsigned* a, const unsigned* b) {
    asm volatile(
        "mma.sync.aligned.m16n8k16.row.col.f32.bf16.bf16.f32 "
        "{%0,%1,%2,%3}, {%4,%5,%6,%7}, {%8,%9}, {%0,%1,%2,%3};\n"
        : "+f"(c[0]), "+f"(c[1]), "+f"(c[2]), "+f"(c[3])
        : "r"(a[0]), "r"(a[1]), "r"(a[2]), "r"(a[3]), "r"(b[0]), "r"(b[1]));
}

#define PITCH   36
#define P_AH    0
#define P_AL    2304
#define P_BH    4608
#define P_BL    6912
#define STAGE_W 9216
#define STAGE_B (STAGE_W * 4)
#define GSMEM   (2 * STAGE_B)

__device__ __forceinline__ void issue_stage(unsigned sdst, int bm, int bn, int kb8, int s, int tid) {
    const uint4* XH4 = (const uint4*)g_xhi;
    const uint4* XL4 = (const uint4*)g_xlo;
    const uint4* WH4 = (const uint4*)g_whi;
    const uint4* WL4 = (const uint4*)g_wlo;
    const int w = tid & 7;
    const int rr = tid >> 3;
    const size_t col = kb8 + s * 8 + w;
    const unsigned d0 = sdst + (unsigned)(P_AH * 4 + (rr * 9 + w) * 16);
    const unsigned d1 = sdst + (unsigned)(P_AH * 4 + ((rr + 32) * 9 + w) * 16);
    const unsigned d2 = sdst + (unsigned)(P_AL * 4 + (rr * 9 + w) * 16);
    const unsigned d3 = sdst + (unsigned)(P_AL * 4 + ((rr + 32) * 9 + w) * 16);
    const unsigned d4 = sdst + (unsigned)(P_BH * 4 + (rr * 9 + w) * 16);
    const unsigned d5 = sdst + (unsigned)(P_BH * 4 + ((rr + 32) * 9 + w) * 16);
    const unsigned d6 = sdst + (unsigned)(P_BL * 4 + (rr * 9 + w) * 16);
    const unsigned d7 = sdst + (unsigned)(P_BL * 4 + ((rr + 32) * 9 + w) * 16);
    CP_ASYNC16(d0, XH4 + (size_t)(bm + rr)      * 256 + col);
    CP_ASYNC16(d1, XH4 + (size_t)(bm + rr + 32) * 256 + col);
    CP_ASYNC16(d2, XL4 + (size_t)(bm + rr)      * 256 + col);
    CP_ASYNC16(d3, XL4 + (size_t)(bm + rr + 32) * 256 + col);
    CP_ASYNC16(d4, WH4 + (size_t)(bn + rr)      * 256 + col);
    CP_ASYNC16(d5, WH4 + (size_t)(bn + rr + 32) * 256 + col);
    CP_ASYNC16(d6, WL4 + (size_t)(bn + rr)      * 256 + col);
    CP_ASYNC16(d7, WL4 + (size_t)(bn + rr + 32) * 256 + col);
}

// ---------------- kernel 1: cp.async + ldmatrix bf16-split tensor GEMM ----------------
__global__ __launch_bounds__(256) void gemm_mma_kernel() {
    extern __shared__ unsigned smem_dyn[];
    const unsigned sbase = smem_to_u32(smem_dyn);
    const int tid  = threadIdx.x;
    const int lane = tid & 31;
    const int warp = tid >> 5;
    const int wm = warp & 3;
    const int wn = warp >> 2;
    const int bm = blockIdx.y * 64;
    const int bn = blockIdx.x * 64;
    const int kb8 = blockIdx.z * (KSLICE / 8);

    float acc[4][4];
    #pragma unroll
    for (int j = 0; j < 4; j++)
        #pragma unroll
        for (int i = 0; i < 4; i++) acc[j][i] = 0.f;

    const int rr8 = lane & 7;
    const int g1  = (lane >> 3) & 1;
    const int g2  = lane >> 4;
    const unsigned aoffAH = (unsigned)((P_AH + (wm * 16 + rr8 + 8 * g1) * PITCH + 4 * g2) * 4);
    const unsigned aoffAL = aoffAH + (unsigned)((P_AL - P_AH) * 4);
    const unsigned boffH0 = (unsigned)((P_BH + (wn * 32 + (0 + g1) * 8 + rr8) * PITCH + 4 * g2) * 4);
    const unsigned boffH1 = (unsigned)((P_BH + (wn * 32 + (2 + g1) * 8 + rr8) * PITCH + 4 * g2) * 4);
    const unsigned boffL0 = boffH0 + (unsigned)((P_BL - P_BH) * 4);
    const unsigned boffL1 = boffH1 + (unsigned)((P_BL - P_BH) * 4);

    issue_stage(sbase, bm, bn, kb8, 0, tid);
    CP_COMMIT();
    CP_WAIT0();
    __syncthreads();

    #pragma unroll
    for (int s = 0; s < 8; s++) {
        if (s + 1 < 8) {
            issue_stage(sbase + ((s + 1) & 1) * STAGE_B, bm, bn, kb8, s + 1, tid);
            CP_COMMIT();
        }

        const unsigned sb = sbase + (s & 1) * STAGE_B;
        #pragma unroll
        for (int t = 0; t < 4; t++) {
            const unsigned ko = (unsigned)(t * 32);
            unsigned ah[4], al[4], bH0[4], bH1[4], bL0[4], bL1[4];
            LDSM_X4(ah[0], ah[1], ah[2], ah[3], sb + aoffAH + ko);
            LDSM_X4(al[0], al[1], al[2], al[3], sb + aoffAL + ko);
            LDSM_X4(bH0[0], bH0[1], bH0[2], bH0[3], sb + boffH0 + ko);
            LDSM_X4(bH1[0], bH1[1], bH1[2], bH1[3], sb + boffH1 + ko);
            LDSM_X4(bL0[0], bL0[1], bL0[2], bL0[3], sb + boffL0 + ko);
            LDSM_X4(bL1[0], bL1[1], bL1[2], bL1[3], sb + boffL1 + ko);

            unsigned b0[2] = {bH0[0], bH0[2]}, b1[2] = {bH0[1], bH0[3]};
            unsigned b2[2] = {bH1[0], bH1[2]}, b3[2] = {bH1[1], bH1[3]};
            unsigned c0[2] = {bL0[0], bL0[2]}, c1[2] = {bL0[1], bL0[3]};
            unsigned c2[2] = {bL1[0], bL1[2]}, c3[2] = {bL1[1], bL1[3]};

            mma16816(acc[0], ah, b0);
            mma16816(acc[1], ah, b1);
            mma16816(acc[2], ah, b2);
            mma16816(acc[3], ah, b3);
            mma16816(acc[0], ah, c0);
            mma16816(acc[1], ah, c1);
            mma16816(acc[2], ah, c2);
            mma16816(acc[3], ah, c3);
            mma16816(acc[0], al, b0);
            mma16816(acc[1], al, b1);
            mma16816(acc[2], al, b2);
            mma16816(acc[3], al, b3);
        }

        if (s + 1 < 8) {
            CP_WAIT0();
            __syncthreads();
        }
    }

    float* dst = g_hpart[blockIdx.z];
    const int r0 = bm + wm * 16 + (lane >> 2);
    #pragma unroll
    for (int j = 0; j < 4; j++) {
        const int c = bn + wn * 32 + j * 8 + 2 * (lane & 3);
        if (c < OUTCH) {
            *(float2*)(dst + (size_t)r0 * OUTCH + c)       = make_float2(acc[j][0], acc[j][1]);
            *(float2*)(dst + (size_t)(r0 + 8) * OUTCH + c) = make_float2(acc[j][2], acc[j][3]);
        }
    }
}

// ---------------- kernel 2: reduce split-K -> g_h + BN affine (A,B) precompute ----------------
__global__ __launch_bounds__(256) void reduce_stats_kernel(const float* __restrict__ gamma,
                                                           const float* __restrict__ beta) {
    __shared__ float ssum[8][32];
    __shared__ float ssq [8][32];
    const int c = threadIdx.x & 31, g = threadIdx.x >> 5;
    const int cg = blockIdx.x * 32 + c;
    const int chunk = blockIdx.y;
    const bool valid = cg < OUTCH;

    float s = 0.f, sq = 0.f;
    if (valid) {
        #pragma unroll 4
        for (int r = 0; r < 40; r++) {
            int row = chunk * CHROWS + g * 40 + r;
            size_t idx = (size_t)row * OUTCH + cg;
            float h = g_hpart[0][idx] + g_hpart[1][idx] + g_hpart[2][idx] + g_hpart[3][idx];
            g_h[idx] = h;
            s += h; sq += h * h;
        }
    }
    ssum[g][c] = s; ssq[g][c] = sq;
    __syncthreads();
    if (g == 0 && valid) {
        float ts = 0.f, tq = 0.f;
        #pragma unroll
        for (int i = 0; i < 8; i++) { ts += ssum[i][c]; tq += ssq[i][c]; }
        float mean = ts * (1.f / CHROWS);
        float var  = tq * (1.f / CHROWS) - mean * mean;
        float A = gamma[cg] * rsqrtf(var + 1e-5f);
        g_sum[chunk * OUTCH + cg] = A;
        g_sq [chunk * OUTCH + cg] = beta[cg] - mean * A;
    }
}

// ---------------- kernel 3: BN affine + prior-mul + q/k/v (coalesced transpose) ----------------
__global__ __launch_bounds__(256) void bn_qkv_kernel(const float* __restrict__ prior,
                                                     const float* __restrict__ ipw,
                                                     const float* __restrict__ ipb) {
    __shared__ float qs[32][33];
    __shared__ float ks[32][33];
    __shared__ float vs[32][33];
    const int tid = threadIdx.x;
    const int ni = tid & 7, li = tid >> 3;
    const int nb = blockIdx.x, lb = blockIdx.y;
    const int n = nb * 8 + ni;
    const int l = lb * 32 + li;

    if (n < NS) {
        const int c0 = n * 4;
        const int chunk = l / CHROWS;
        float4 Ar = *(const float4*)(g_sum + chunk * OUTCH + c0);
        float4 Br = *(const float4*)(g_sq  + chunk * OUTCH + c0);
        float4 hr = *(const float4*)(g_h + (size_t)l * OUTCH + c0);
        float4 pr = *(const float4*)(prior + (size_t)l * OUTCH + c0);
        float Av[4] = {Ar.x, Ar.y, Ar.z, Ar.w};
        float Bv[4] = {Br.x, Br.y, Br.z, Br.w};
        float hv[4] = {hr.x, hr.y, hr.z, hr.w};
        float pv[4] = {pr.x, pr.y, pr.z, pr.w};
        float hm[4];
        #pragma unroll
        for (int e = 0; e < 4; e++)
            hm[e] = pv[e] * fmaf(hv[e], Av[e], Bv[e]);
        *(float4*)(g_hmul + (size_t)l * OUTCH + c0) = make_float4(hm[0], hm[1], hm[2], hm[3]);
        #pragma unroll
        for (int e = 0; e < 4; e++) {
            float q = ipb[e], k = ipb[4 + e], v = ipb[8 + e];
            #pragma unroll
            for (int e2 = 0; e2 < 4; e2++) {
                q = fmaf(ipw[e * 4 + e2],       hm[e2], q);
                k = fmaf(ipw[(4 + e) * 4 + e2], pv[e2], k);
                v = fmaf(ipw[(8 + e) * 4 + e2], pv[e2], v);
            }
            qs[ni * 4 + e][li] = q * LOG2E;
            ks[ni * 4 + e][li] = k;
            vs[ni * 4 + e][li] = v;
        }
    }
    __syncthreads();
    const int lo = tid & 31;
    #pragma unroll
    for (int p = 0; p < 4; p++) {
        int cl = (tid >> 5) + p * 8;
        int cc = nb * 32 + cl;
        if (cc < OUTCH) {
            size_t off = (size_t)cc * BSZ + lb * 32 + lo;
            g_q[off] = qs[cl][lo];
            g_k[off] = ks[cl][lo];
            g_v[off] = vs[cl][lo];
        }
    }
}

// ---------------- kernel 4: per-channel attention, pipe-specialized blocks ----------------
// 3/4 of channel-blocks: proven pure-MUFU f32x2 path. 1/4: pure-FMA poly path.
// Co-resident CTAs saturate MUFU and FMA pipes concurrently.
__global__ __launch_bounds__(640) void attn_kernel() {
    __shared__ __align__(16) float ks[BSZ];
    __shared__ __align__(16) float vs[BSZ];
    const int c = blockIdx.x, t = threadIdx.x;
    ks[t] = g_k[(size_t)c * BSZ + t];
    vs[t] = g_v[(size_t)c * BSZ + t];
    __syncthreads();

    const float ql = g_q[(size_t)c * BSZ + t];
    float result;

    if ((c & 3) == 3) {
        // ---- FMA-pipe poly path ----
        float d0 = 0.f, d1 = 0.f, d2 = 0.f, d3 = 0.f;
        float m0 = 0.f, m1 = 0.f, m2 = 0.f, m3 = 0.f;
        const float4* k4 = (const float4*)ks;
        const float4* v4 = (const float4*)vs;
        #pragma unroll 4
        for (int s = 0; s < BSZ / 4; s++) {
            float4 kk = k4[s], vv = v4[s];
            float e0 = exp2_poly(ql * kk.x);
            float e1 = exp2_poly(ql * kk.y);
            float e2 = exp2_poly(ql * kk.z);
            float e3 = exp2_poly(ql * kk.w);
            d0 += e0; d1 += e1; d2 += e2; d3 += e3;
            m0 = fmaf(e0, vv.x, m0);
            m1 = fmaf(e1, vv.y, m1);
            m2 = fmaf(e2, vv.z, m2);
            m3 = fmaf(e3, vv.w, m3);
        }
        result = ((m0 + m1) + (m2 + m3)) / ((d0 + d1) + (d2 + d3));
    } else {
        // ---- proven pure-MUFU f32x2 path ----
        unsigned long long qq;
        asm("mov.b64 %0, {%1, %1};" : "=l"(qq) : "f"(ql));
        unsigned long long d01 = 0ull, d23 = 0ull, n01 = 0ull, n23 = 0ull;
        const ulonglong2* k2 = (const ulonglong2*)ks;
        const ulonglong2* v2 = (const ulonglong2*)vs;
        #pragma unroll 4
        for (int s = 0; s < BSZ / 4; s++) {
            ulonglong2 kk = k2[s], vv = v2[s];
            unsigned long long p01, p23;
            asm("mul.rn.f32x2 %0, %1, %2;" : "=l"(p01) : "l"(kk.x), "l"(qq));
            asm("mul.rn.f32x2 %0, %1, %2;" : "=l"(p23) : "l"(kk.y), "l"(qq));
            float x0, x1, x2, x3;
            asm("mov.b64 {%0, %1}, %2;" : "=f"(x0), "=f"(x1) : "l"(p01));
            asm("mov.b64 {%0, %1}, %2;" : "=f"(x2), "=f"(x3) : "l"(p23));
            float e0 = ex2(x0), e1 = ex2(x1), e2 = ex2(x2), e3 = ex2(x3);
            unsigned long long e01, e23;
            asm("mov.b64 %0, {%1, %2};" : "=l"(e01) : "f"(e0), "f"(e1));
            asm("mov.b64 %0, {%1, %2};" : "=l"(e23) : "f"(e2), "f"(e3));
            asm("add.rn.f32x2 %0, %0, %1;" : "+l"(d01) : "l"(e01));
            asm("add.rn.f32x2 %0, %0, %1;" : "+l"(d23) : "l"(e23));
            asm("fma.rn.f32x2 %0, %1, %2, %0;" : "+l"(n01) : "l"(e01), "l"(vv.x));
            asm("fma.rn.f32x2 %0, %1, %2, %0;" : "+l"(n23) : "l"(e23), "l"(vv.y));
        }
        float da, db, dc, dd, na, nb, nc, nd;
        asm("mov.b64 {%0, %1}, %2;" : "=f"(da), "=f"(db) : "l"(d01));
        asm("mov.b64 {%0, %1}, %2;" : "=f"(dc), "=f"(dd) : "l"(d23));
        asm("mov.b64 {%0, %1}, %2;" : "=f"(na), "=f"(nb) : "l"(n01));
        asm("mov.b64 {%0, %1}, %2;" : "=f"(nc), "=f"(nd) : "l"(n23));
        result = ((na + nb) + (nc + nd)) / ((da + db) + (dc + dd));
    }
    // transposed store: [l][c] — scattered (absorbed by idle LSU), epi reads coalesced
    g_o[(size_t)t * OUTCH + c] = result;
}

// ---------------- kernel 5: out_proj + residual + row softmax (coalesced g_o reads) --------
__global__ __launch_bounds__(256) void epi_kernel(const float* __restrict__ opw,
                                                  const float* __restrict__ opb,
                                                  float* __restrict__ out) {
    __shared__ float orow[OUTCH];
    __shared__ float sh[OUTCH];
    __shared__ float rbuf[8];
    const int l = blockIdx.x, tid = threadIdx.x;

    for (int c = tid; c < OUTCH; c += 256) orow[c] = g_o[(size_t)l * OUTCH + c];
    __syncthreads();

    float lmax = -1e30f;
    for (int c = tid; c < OUTCH; c += 256) {
        int n = c >> 2, e = c & 3;
        float y = opb[e];
        #pragma unroll
        for (int e2 = 0; e2 < 4; e2++) y = fmaf(opw[e * 4 + e2], orow[n * 4 + e2], y);
        float lg = g_hmul[(size_t)l * OUTCH + c] + y;
        sh[c] = lg;
        lmax = fmaxf(lmax, lg);
    }
    #pragma unroll
    for (int o = 16; o; o >>= 1) lmax = fmaxf(lmax, __shfl_xor_sync(0xFFFFFFFFu, lmax, o));
    if ((tid & 31) == 0) rbuf[tid >> 5] = lmax;
    __syncthreads();
    float bmax = rbuf[0];
    #pragma unroll
    for (int i = 1; i < 8; i++) bmax = fmaxf(bmax, rbuf[i]);
    __syncthreads();

    float sum = 0.f;
    for (int c = tid; c < OUTCH; c += 256) {
        float e = ex2((sh[c] - bmax) * LOG2E);
        sh[c] = e;
        sum += e;
    }
    #pragma unroll
    for (int o = 16; o; o >>= 1) sum += __shfl_xor_sync(0xFFFFFFFFu, sum, o);
    if ((tid & 31) == 0) rbuf[tid >> 5] = sum;
    __syncthreads();
    float bsum = 0.f;
    #pragma unroll
    for (int i = 0; i < 8; i++) bsum += rbuf[i];
    float inv = 1.f / bsum;
    for (int c = tid; c < OUTCH; c += 256) out[(size_t)l * OUTCH + c] = sh[c] * inv;
}

// ---------------- launch ----------------
extern "C" void kernel_launch(void* const* d_in, const int* in_sizes, int n_in,
                              void* d_out, int out_size) {
    const float* x     = (const float*)d_in[0];
    const float* prior = (const float*)d_in[1];
    const float* w_lin = (const float*)d_in[2];
    const float* gamma = (const float*)d_in[3];
    const float* beta  = (const float*)d_in[4];
    const float* ipw   = (const float*)d_in[5];
    const float* ipb   = (const float*)d_in[6];
    const float* opw   = (const float*)d_in[7];
    const float* opb   = (const float*)d_in[8];
    float* out = (float*)d_out;

    cudaFuncSetAttribute(gemm_mma_kernel, cudaFuncAttributeMaxDynamicSharedMemorySize, GSMEM);

    prep_kernel<<<(BSZ * INCH / 4 + WROWS * INCH / 4) / 256, 256>>>(x, w_lin);
    gemm_mma_kernel<<<dim3(WROWS / 64, BSZ / 64, KSPLIT), 256, GSMEM>>>();
    reduce_stats_kernel<<<dim3((OUTCH + 31) / 32, 2), 256>>>(gamma, beta);
    bn_qkv_kernel<<<dim3((NS + 7) / 8, BSZ / 32), 256>>>(prior, ipw, ipb);
    attn_kernel<<<OUTCH, BSZ>>>();
    epi_kernel<<<BSZ, 256>>>(opw, opb, out);
}

// round 16
// speedup vs baseline: 1.2750x; 1.2750x over previous
#include <cuda_runtime.h>
#include <cuda_bf16.h>

#define BSZ    640
#define INCH   2048
#define OUTCH  696
#define NS     174
#define CHROWS 320
#define WROWS  704              // OUTCH padded to 64
#define KSPLIT 4
#define KSLICE (INCH / KSPLIT)  // 512

// ---------------- scratch ----------------
__device__ __nv_bfloat16 g_xhi[BSZ * INCH];
__device__ __nv_bfloat16 g_xlo[BSZ * INCH];
__device__ __nv_bfloat16 g_whi[WROWS * INCH];
__device__ __nv_bfloat16 g_wlo[WROWS * INCH];
__device__ float g_hpart[KSPLIT][BSZ * OUTCH];
__device__ float g_h   [BSZ * OUTCH];
__device__ float g_hmul[BSZ * OUTCH];
__device__ float g_o   [BSZ * OUTCH];   // [l][c] — epi reads coalesced
__device__ float g_sum [2 * OUTCH];     // after reduce: BN affine scale A
__device__ float g_sq  [2 * OUTCH];     // after reduce: BN affine shift B

#define LOG2E 1.4426950408889634f

__device__ __forceinline__ float ex2(float x) {
    float y;
    asm("ex2.approx.ftz.f32 %0, %1;" : "=f"(y) : "f"(x));
    return y;
}

__device__ __forceinline__ unsigned smem_to_u32(const void* p) {
    unsigned a;
    asm("{ .reg .u64 t; cvta.to.shared.u64 t, %1; cvt.u32.u64 %0, t; }" : "=r"(a) : "l"(p));
    return a;
}

#define CP_ASYNC16(dst_u32, src_ptr) \
    asm volatile("cp.async.cg.shared.global [%0], [%1], 16;" :: "r"(dst_u32), "l"(src_ptr) : "memory")
#define CP_COMMIT() asm volatile("cp.async.commit_group;" ::: "memory")
#define CP_WAIT0()  asm volatile("cp.async.wait_group 0;" ::: "memory")

#define LDSM_X4(r0, r1, r2, r3, addr) \
    asm volatile("ldmatrix.sync.aligned.m8n8.x4.shared.b16 {%0,%1,%2,%3}, [%4];" \
        : "=r"(r0), "=r"(r1), "=r"(r2), "=r"(r3) : "r"(addr))

// ---------------- kernel 0: fp32 -> bf16 hi/lo split ----------------
__global__ __launch_bounds__(256) void prep_kernel(const float* __restrict__ x,
                                                   const float* __restrict__ w) {
    const int gid = blockIdx.x * 256 + threadIdx.x;
    const int XQ = BSZ * INCH / 4;
    const int WQ = WROWS * INCH / 4;
    float4 v;
    uint2 *hid, *lod;
    if (gid < XQ) {
        v = ((const float4*)x)[gid];
        hid = (uint2*)g_xhi + gid; lod = (uint2*)g_xlo + gid;
    } else {
        int q = gid - XQ;
        if (q >= WQ) return;
        v = (q < OUTCH * (INCH / 4)) ? ((const float4*)w)[q] : make_float4(0.f, 0.f, 0.f, 0.f);
        hid = (uint2*)g_whi + q; lod = (uint2*)g_wlo + q;
    }
    float fv[4] = {v.x, v.y, v.z, v.w};
    unsigned short hs[4], ls[4];
    #pragma unroll
    for (int i = 0; i < 4; i++) {
        __nv_bfloat16 h = __float2bfloat16(fv[i]);
        __nv_bfloat16 l = __float2bfloat16(fv[i] - __bfloat162float(h));
        hs[i] = __bfloat16_as_ushort(h);
        ls[i] = __bfloat16_as_ushort(l);
    }
    uint2 H, L;
    H.x = ((unsigned)hs[1] << 16) | hs[0]; H.y = ((unsigned)hs[3] << 16) | hs[2];
    L.x = ((unsigned)ls[1] << 16) | ls[0]; L.y = ((unsigned)ls[3] << 16) | ls[2];
    *hid = H; *lod = L;
}

// ---------------- mma.sync m16n8k16 bf16 ----------------
__device__ __forceinline__ void mma16816(float* c, const unsigned* a, const unsigned* b) {
    asm volatile(
        "mma.sync.aligned.m16n8k16.row.col.f32.bf16.bf16.f32 "
        "{%0,%1,%2,%3}, {%4,%5,%6,%7}, {%8,%9}, {%0,%1,%2,%3};\n"
        : "+f"(c[0]), "+f"(c[1]), "+f"(c[2]), "+f"(c[3])
        : "r"(a[0]), "r"(a[1]), "r"(a[2]), "r"(a[3]), "r"(b[0]), "r"(b[1]));
}

#define PITCH   36
#define P_AH    0
#define P_AL    2304
#define P_BH    4608
#define P_BL    6912
#define STAGE_W 9216
#define STAGE_B (STAGE_W * 4)
#define GSMEM   (2 * STAGE_B)

__device__ __forceinline__ void issue_stage(unsigned sdst, int bm, int bn, int kb8, int s, int tid) {
    const uint4* XH4 = (const uint4*)g_xhi;
    const uint4* XL4 = (const uint4*)g_xlo;
    const uint4* WH4 = (const uint4*)g_whi;
    const uint4* WL4 = (const uint4*)g_wlo;
    const int w = tid & 7;
    const int rr = tid >> 3;
    const size_t col = kb8 + s * 8 + w;
    const unsigned d0 = sdst + (unsigned)(P_AH * 4 + (rr * 9 + w) * 16);
    const unsigned d1 = sdst + (unsigned)(P_AH * 4 + ((rr + 32) * 9 + w) * 16);
    const unsigned d2 = sdst + (unsigned)(P_AL * 4 + (rr * 9 + w) * 16);
    const unsigned d3 = sdst + (unsigned)(P_AL * 4 + ((rr + 32) * 9 + w) * 16);
    const unsigned d4 = sdst + (unsigned)(P_BH * 4 + (rr * 9 + w) * 16);
    const unsigned d5 = sdst + (unsigned)(P_BH * 4 + ((rr + 32) * 9 + w) * 16);
    const unsigned d6 = sdst + (unsigned)(P_BL * 4 + (rr * 9 + w) * 16);
    const unsigned d7 = sdst + (unsigned)(P_BL * 4 + ((rr + 32) * 9 + w) * 16);
    CP_ASYNC16(d0, XH4 + (size_t)(bm + rr)      * 256 + col);
    CP_ASYNC16(d1, XH4 + (size_t)(bm + rr + 32) * 256 + col);
    CP_ASYNC16(d2, XL4 + (size_t)(bm + rr)      * 256 + col);
    CP_ASYNC16(d3, XL4 + (size_t)(bm + rr + 32) * 256 + col);
    CP_ASYNC16(d4, WH4 + (size_t)(bn + rr)      * 256 + col);
    CP_ASYNC16(d5, WH4 + (size_t)(bn + rr + 32) * 256 + col);
    CP_ASYNC16(d6, WL4 + (size_t)(bn + rr)      * 256 + col);
    CP_ASYNC16(d7, WL4 + (size_t)(bn + rr + 32) * 256 + col);
}

// ---------------- kernel 1: cp.async + ldmatrix bf16-split tensor GEMM ----------------
__global__ __launch_bounds__(256) void gemm_mma_kernel() {
    extern __shared__ unsigned smem_dyn[];
    const unsigned sbase = smem_to_u32(smem_dyn);
    const int tid  = threadIdx.x;
    const int lane = tid & 31;
    const int warp = tid >> 5;
    const int wm = warp & 3;
    const int wn = warp >> 2;
    const int bm = blockIdx.y * 64;
    const int bn = blockIdx.x * 64;
    const int kb8 = blockIdx.z * (KSLICE / 8);

    float acc[4][4];
    #pragma unroll
    for (int j = 0; j < 4; j++)
        #pragma unroll
        for (int i = 0; i < 4; i++) acc[j][i] = 0.f;

    const int rr8 = lane & 7;
    const int g1  = (lane >> 3) & 1;
    const int g2  = lane >> 4;
    const unsigned aoffAH = (unsigned)((P_AH + (wm * 16 + rr8 + 8 * g1) * PITCH + 4 * g2) * 4);
    const unsigned aoffAL = aoffAH + (unsigned)((P_AL - P_AH) * 4);
    const unsigned boffH0 = (unsigned)((P_BH + (wn * 32 + (0 + g1) * 8 + rr8) * PITCH + 4 * g2) * 4);
    const unsigned boffH1 = (unsigned)((P_BH + (wn * 32 + (2 + g1) * 8 + rr8) * PITCH + 4 * g2) * 4);
    const unsigned boffL0 = boffH0 + (unsigned)((P_BL - P_BH) * 4);
    const unsigned boffL1 = boffH1 + (unsigned)((P_BL - P_BH) * 4);

    issue_stage(sbase, bm, bn, kb8, 0, tid);
    CP_COMMIT();
    CP_WAIT0();
    __syncthreads();

    #pragma unroll
    for (int s = 0; s < 8; s++) {
        if (s + 1 < 8) {
            issue_stage(sbase + ((s + 1) & 1) * STAGE_B, bm, bn, kb8, s + 1, tid);
            CP_COMMIT();
        }

        const unsigned sb = sbase + (s & 1) * STAGE_B;
        #pragma unroll
        for (int t = 0; t < 4; t++) {
            const unsigned ko = (unsigned)(t * 32);
            unsigned ah[4], al[4], bH0[4], bH1[4], bL0[4], bL1[4];
            LDSM_X4(ah[0], ah[1], ah[2], ah[3], sb + aoffAH + ko);
            LDSM_X4(al[0], al[1], al[2], al[3], sb + aoffAL + ko);
            LDSM_X4(bH0[0], bH0[1], bH0[2], bH0[3], sb + boffH0 + ko);
            LDSM_X4(bH1[0], bH1[1], bH1[2], bH1[3], sb + boffH1 + ko);
            LDSM_X4(bL0[0], bL0[1], bL0[2], bL0[3], sb + boffL0 + ko);
            LDSM_X4(bL1[0], bL1[1], bL1[2], bL1[3], sb + boffL1 + ko);

            unsigned b0[2] = {bH0[0], bH0[2]}, b1[2] = {bH0[1], bH0[3]};
            unsigned b2[2] = {bH1[0], bH1[2]}, b3[2] = {bH1[1], bH1[3]};
            unsigned c0[2] = {bL0[0], bL0[2]}, c1[2] = {bL0[1], bL0[3]};
            unsigned c2[2] = {bL1[0], bL1[2]}, c3[2] = {bL1[1], bL1[3]};

            mma16816(acc[0], ah, b0);
            mma16816(acc[1], ah, b1);
            mma16816(acc[2], ah, b2);
            mma16816(acc[3], ah, b3);
            mma16816(acc[0], ah, c0);
            mma16816(acc[1], ah, c1);
            mma16816(acc[2], ah, c2);
            mma16816(acc[3], ah, c3);
            mma16816(acc[0], al, b0);
            mma16816(acc[1], al, b1);
            mma16816(acc[2], al, b2);
            mma16816(acc[3], al, b3);
        }

        if (s + 1 < 8) {
            CP_WAIT0();
            __syncthreads();
        }
    }

    float* dst = g_hpart[blockIdx.z];
    const int r0 = bm + wm * 16 + (lane >> 2);
    #pragma unroll
    for (int j = 0; j < 4; j++) {
        const int c = bn + wn * 32 + j * 8 + 2 * (lane & 3);
        if (c < OUTCH) {
            *(float2*)(dst + (size_t)r0 * OUTCH + c)       = make_float2(acc[j][0], acc[j][1]);
            *(float2*)(dst + (size_t)(r0 + 8) * OUTCH + c) = make_float2(acc[j][2], acc[j][3]);
        }
    }
}

// ---------------- kernel 2: reduce split-K -> g_h + BN affine (A,B) precompute ----------------
__global__ __launch_bounds__(256) void reduce_stats_kernel(const float* __restrict__ gamma,
                                                           const float* __restrict__ beta) {
    __shared__ float ssum[8][32];
    __shared__ float ssq [8][32];
    const int c = threadIdx.x & 31, g = threadIdx.x >> 5;
    const int cg = blockIdx.x * 32 + c;
    const int chunk = blockIdx.y;
    const bool valid = cg < OUTCH;

    float s = 0.f, sq = 0.f;
    if (valid) {
        #pragma unroll 4
        for (int r = 0; r < 40; r++) {
            int row = chunk * CHROWS + g * 40 + r;
            size_t idx = (size_t)row * OUTCH + cg;
            float h = g_hpart[0][idx] + g_hpart[1][idx] + g_hpart[2][idx] + g_hpart[3][idx];
            g_h[idx] = h;
            s += h; sq += h * h;
        }
    }
    ssum[g][c] = s; ssq[g][c] = sq;
    __syncthreads();
    if (g == 0 && valid) {
        float ts = 0.f, tq = 0.f;
        #pragma unroll
        for (int i = 0; i < 8; i++) { ts += ssum[i][c]; tq += ssq[i][c]; }
        float mean = ts * (1.f / CHROWS);
        float var  = tq * (1.f / CHROWS) - mean * mean;
        float A = gamma[cg] * rsqrtf(var + 1e-5f);
        g_sum[chunk * OUTCH + cg] = A;
        g_sq [chunk * OUTCH + cg] = beta[cg] - mean * A;
    }
}

// ---------------- kernel 3: FUSED BN affine + qkv projection + per-channel attention -------
// block c (696 blocks, 640 threads, thread t = query/key row l).
// Each thread computes its own q/k/v from g_h + prior + A/B + 4x4 projections; k/v shared
// via smem; then the proven pure-MUFU f32x2 softmax-attention loop.
// Block with (c&3)==0 also writes g_hmul for its 4 channels (consumed by epi).
__global__ __launch_bounds__(640) void attn_kernel(const float* __restrict__ prior,
                                                   const float* __restrict__ ipw,
                                                   const float* __restrict__ ipb) {
    __shared__ __align__(16) float ks[BSZ];
    __shared__ __align__(16) float vs[BSZ];
    const int c = blockIdx.x, t = threadIdx.x;
    const int n = c >> 2, e = c & 3;
    const int c0 = n * 4;
    const int chunk = (t >= CHROWS) ? 1 : 0;

    // per-thread BN affine + prior-mul for this group's 4 channels
    float4 A4 = *(const float4*)(g_sum + chunk * OUTCH + c0);
    float4 B4 = *(const float4*)(g_sq  + chunk * OUTCH + c0);
    float4 h4 = *(const float4*)(g_h   + (size_t)t * OUTCH + c0);
    float4 p4 = *(const float4*)(prior + (size_t)t * OUTCH + c0);
    float hm[4], pv[4];
    pv[0] = p4.x; pv[1] = p4.y; pv[2] = p4.z; pv[3] = p4.w;
    hm[0] = pv[0] * fmaf(h4.x, A4.x, B4.x);
    hm[1] = pv[1] * fmaf(h4.y, A4.y, B4.y);
    hm[2] = pv[2] * fmaf(h4.z, A4.z, B4.z);
    hm[3] = pv[3] * fmaf(h4.w, A4.w, B4.w);

    if (e == 0)   // one block per group persists hmul for the epilogue
        *(float4*)(g_hmul + (size_t)t * OUTCH + c0) = make_float4(hm[0], hm[1], hm[2], hm[3]);

    // q/k/v for this channel
    float q = ipb[e], k = ipb[4 + e], v = ipb[8 + e];
    #pragma unroll
    for (int e2 = 0; e2 < 4; e2++) {
        q = fmaf(ipw[e * 4 + e2],       hm[e2], q);
        k = fmaf(ipw[(4 + e) * 4 + e2], pv[e2], k);
        v = fmaf(ipw[(8 + e) * 4 + e2], pv[e2], v);
    }
    ks[t] = k;
    vs[t] = v;
    __syncthreads();

    const float ql = q * LOG2E;
    unsigned long long qq;
    asm("mov.b64 %0, {%1, %1};" : "=l"(qq) : "f"(ql));
    unsigned long long d01 = 0ull, d23 = 0ull, n01 = 0ull, n23 = 0ull;
    const ulonglong2* k2 = (const ulonglong2*)ks;
    const ulonglong2* v2 = (const ulonglong2*)vs;
    #pragma unroll 4
    for (int s = 0; s < BSZ / 4; s++) {
        ulonglong2 kk = k2[s], vv = v2[s];
        unsigned long long p01, p23;
        asm("mul.rn.f32x2 %0, %1, %2;" : "=l"(p01) : "l"(kk.x), "l"(qq));
        asm("mul.rn.f32x2 %0, %1, %2;" : "=l"(p23) : "l"(kk.y), "l"(qq));
        float x0, x1, x2, x3;
        asm("mov.b64 {%0, %1}, %2;" : "=f"(x0), "=f"(x1) : "l"(p01));
        asm("mov.b64 {%0, %1}, %2;" : "=f"(x2), "=f"(x3) : "l"(p23));
        float e0 = ex2(x0), e1 = ex2(x1), e2 = ex2(x2), e3 = ex2(x3);
        unsigned long long e01, e23;
        asm("mov.b64 %0, {%1, %2};" : "=l"(e01) : "f"(e0), "f"(e1));
        asm("mov.b64 %0, {%1, %2};" : "=l"(e23) : "f"(e2), "f"(e3));
        asm("add.rn.f32x2 %0, %0, %1;" : "+l"(d01) : "l"(e01));
        asm("add.rn.f32x2 %0, %0, %1;" : "+l"(d23) : "l"(e23));
        asm("fma.rn.f32x2 %0, %1, %2, %0;" : "+l"(n01) : "l"(e01), "l"(vv.x));
        asm("fma.rn.f32x2 %0, %1, %2, %0;" : "+l"(n23) : "l"(e23), "l"(vv.y));
    }
    float da, db, dc, dd, na, nb, nc, nd;
    asm("mov.b64 {%0, %1}, %2;" : "=f"(da), "=f"(db) : "l"(d01));
    asm("mov.b64 {%0, %1}, %2;" : "=f"(dc), "=f"(dd) : "l"(d23));
    asm("mov.b64 {%0, %1}, %2;" : "=f"(na), "=f"(nb) : "l"(n01));
    asm("mov.b64 {%0, %1}, %2;" : "=f"(nc), "=f"(nd) : "l"(n23));
    // transposed store: [l][c] — scattered stores (idle LSU), epi reads coalesced
    g_o[(size_t)t * OUTCH + c] = ((na + nb) + (nc + nd)) / ((da + db) + (dc + dd));
}

// ---------------- kernel 4: out_proj + residual + row softmax (coalesced g_o reads) --------
__global__ __launch_bounds__(256) void epi_kernel(const float* __restrict__ opw,
                                                  const float* __restrict__ opb,
                                                  float* __restrict__ out) {
    __shared__ float orow[OUTCH];
    __shared__ float sh[OUTCH];
    __shared__ float rbuf[8];
    const int l = blockIdx.x, tid = threadIdx.x;

    for (int c = tid; c < OUTCH; c += 256) orow[c] = g_o[(size_t)l * OUTCH + c];
    __syncthreads();

    float lmax = -1e30f;
    for (int c = tid; c < OUTCH; c += 256) {
        int n = c >> 2, e = c & 3;
        float y = opb[e];
        #pragma unroll
        for (int e2 = 0; e2 < 4; e2++) y = fmaf(opw[e * 4 + e2], orow[n * 4 + e2], y);
        float lg = g_hmul[(size_t)l * OUTCH + c] + y;
        sh[c] = lg;
        lmax = fmaxf(lmax, lg);
    }
    #pragma unroll
    for (int o = 16; o; o >>= 1) lmax = fmaxf(lmax, __shfl_xor_sync(0xFFFFFFFFu, lmax, o));
    if ((tid & 31) == 0) rbuf[tid >> 5] = lmax;
    __syncthreads();
    float bmax = rbuf[0];
    #pragma unroll
    for (int i = 1; i < 8; i++) bmax = fmaxf(bmax, rbuf[i]);
    __syncthreads();

    float sum = 0.f;
    for (int c = tid; c < OUTCH; c += 256) {
        float e = ex2((sh[c] - bmax) * LOG2E);
        sh[c] = e;
        sum += e;
    }
    #pragma unroll
    for (int o = 16; o; o >>= 1) sum += __shfl_xor_sync(0xFFFFFFFFu, sum, o);
    if ((tid & 31) == 0) rbuf[tid >> 5] = sum;
    __syncthreads();
    float bsum = 0.f;
    #pragma unroll
    for (int i = 0; i < 8; i++) bsum += rbuf[i];
    float inv = 1.f / bsum;
    for (int c = tid; c < OUTCH; c += 256) out[(size_t)l * OUTCH + c] = sh[c] * inv;
}

// ---------------- launch ----------------
extern "C" void kernel_launch(void* const* d_in, const int* in_sizes, int n_in,
                              void* d_out, int out_size) {
    const float* x     = (const float*)d_in[0];
    const float* prior = (const float*)d_in[1];
    const float* w_lin = (const float*)d_in[2];
    const float* gamma = (const float*)d_in[3];
    const float* beta  = (const float*)d_in[4];
    const float* ipw   = (const float*)d_in[5];
    const float* ipb   = (const float*)d_in[6];
    const float* opw   = (const float*)d_in[7];
    const float* opb   = (const float*)d_in[8];
    float* out = (float*)d_out;

    cudaFuncSetAttribute(gemm_mma_kernel, cudaFuncAttributeMaxDynamicSharedMemorySize, GSMEM);

    prep_kernel<<<(BSZ * INCH / 4 + WROWS * INCH / 4) / 256, 256>>>(x, w_lin);
    gemm_mma_kernel<<<dim3(WROWS / 64, BSZ / 64, KSPLIT), 256, GSMEM>>>();
    reduce_stats_kernel<<<dim3((OUTCH + 31) / 32, 2), 256>>>(gamma, beta);
    attn_kernel<<<OUTCH, BSZ>>>(prior, ipw, ipb);
    epi_kernel<<<BSZ, 256>>>(opw, opb, out);
}

// round 17
// speedup vs baseline: 1.5012x; 1.1774x over previous
#include <cuda_runtime.h>
#include <cuda_bf16.h>

#define BSZ    640
#define INCH   2048
#define OUTCH  696
#define NGRP   174              // OUTCH / 4
#define CHROWS 320
#define WROWS  704              // OUTCH padded to 64
#define KSPLIT 4
#define KSLICE (INCH / KSPLIT)  // 512

// ---------------- scratch ----------------
__device__ __nv_bfloat16 g_xhi[BSZ * INCH];
__device__ __nv_bfloat16 g_xlo[BSZ * INCH];
__device__ __nv_bfloat16 g_whi[WROWS * INCH];
__device__ __nv_bfloat16 g_wlo[WROWS * INCH];
// split-K partials, GROUP-TRANSPOSED: hpart[s][(n*640 + row)*4 + e]
__device__ float g_hpart[KSPLIT][(WROWS / 4) * BSZ * 4];
__device__ float g_pgrp[NGRP * BSZ * 4];   // prior, group-transposed [(n*640+l)*4+e]
__device__ float g_hmul[BSZ * OUTCH];
__device__ float g_o   [BSZ * OUTCH];      // [l][c] — epi reads coalesced

#define LOG2E 1.4426950408889634f

__device__ __forceinline__ float ex2(float x) {
    float y;
    asm("ex2.approx.ftz.f32 %0, %1;" : "=f"(y) : "f"(x));
    return y;
}

__device__ __forceinline__ unsigned smem_to_u32(const void* p) {
    unsigned a;
    asm("{ .reg .u64 t; cvta.to.shared.u64 t, %1; cvt.u32.u64 %0, t; }" : "=r"(a) : "l"(p));
    return a;
}

#define CP_ASYNC16(dst_u32, src_ptr) \
    asm volatile("cp.async.cg.shared.global [%0], [%1], 16;" :: "r"(dst_u32), "l"(src_ptr) : "memory")
#define CP_COMMIT() asm volatile("cp.async.commit_group;" ::: "memory")
#define CP_WAIT0()  asm volatile("cp.async.wait_group 0;" ::: "memory")

#define LDSM_X4(r0, r1, r2, r3, addr) \
    asm volatile("ldmatrix.sync.aligned.m8n8.x4.shared.b16 {%0,%1,%2,%3}, [%4];" \
        : "=r"(r0), "=r"(r1), "=r"(r2), "=r"(r3) : "r"(addr))

// ---------------- kernel 0: bf16 hi/lo split + prior group-transpose ----------------
#define XQ (BSZ * INCH / 4)
#define WQ (WROWS * INCH / 4)
#define PQ (BSZ * NGRP)
__global__ __launch_bounds__(256) void prep_kernel(const float* __restrict__ x,
                                                   const float* __restrict__ w,
                                                   const float* __restrict__ prior) {
    const int gid = blockIdx.x * 256 + threadIdx.x;
    if (gid >= XQ + WQ) {                      // prior transpose range
        int r = gid - XQ - WQ;
        if (r >= PQ) return;
        int n = r % NGRP, l = r / NGRP;
        float4 p = *(const float4*)(prior + (size_t)l * OUTCH + n * 4);
        ((float4*)g_pgrp)[n * BSZ + l] = p;
        return;
    }
    float4 v;
    uint2 *hid, *lod;
    if (gid < XQ) {
        v = ((const float4*)x)[gid];
        hid = (uint2*)g_xhi + gid; lod = (uint2*)g_xlo + gid;
    } else {
        int q = gid - XQ;
        v = (q < OUTCH * (INCH / 4)) ? ((const float4*)w)[q] : make_float4(0.f, 0.f, 0.f, 0.f);
        hid = (uint2*)g_whi + q; lod = (uint2*)g_wlo + q;
    }
    float fv[4] = {v.x, v.y, v.z, v.w};
    unsigned short hs[4], ls[4];
    #pragma unroll
    for (int i = 0; i < 4; i++) {
        __nv_bfloat16 h = __float2bfloat16(fv[i]);
        __nv_bfloat16 l = __float2bfloat16(fv[i] - __bfloat162float(h));
        hs[i] = __bfloat16_as_ushort(h);
        ls[i] = __bfloat16_as_ushort(l);
    }
    uint2 H, L;
    H.x = ((unsigned)hs[1] << 16) | hs[0]; H.y = ((unsigned)hs[3] << 16) | hs[2];
    L.x = ((unsigned)ls[1] << 16) | ls[0]; L.y = ((unsigned)ls[3] << 16) | ls[2];
    *hid = H; *lod = L;
}

// ---------------- mma.sync m16n8k16 bf16 ----------------
__device__ __forceinline__ void mma16816(float* c, const unsigned* a, const unsigned* b) {
    asm volatile(
        "mma.sync.aligned.m16n8k16.row.col.f32.bf16.bf16.f32 "
        "{%0,%1,%2,%3}, {%4,%5,%6,%7}, {%8,%9}, {%0,%1,%2,%3};\n"
        : "+f"(c[0]), "+f"(c[1]), "+f"(c[2]), "+f"(c[3])
        : "r"(a[0]), "r"(a[1]), "r"(a[2]), "r"(a[3]), "r"(b[0]), "r"(b[1]));
}

#define PITCH   36
#define P_AH    0
#define P_AL    2304
#define P_BH    4608
#define P_BL    6912
#define STAGE_W 9216
#define STAGE_B (STAGE_W * 4)
#define GSMEM   (2 * STAGE_B)

__device__ __forceinline__ void issue_stage(unsigned sdst, int bm, int bn, int kb8, int s, int tid) {
    const uint4* XH4 = (const uint4*)g_xhi;
    const uint4* XL4 = (const uint4*)g_xlo;
    const uint4* WH4 = (const uint4*)g_whi;
    const uint4* WL4 = (const uint4*)g_wlo;
    const int w = tid & 7;
    const int rr = tid >> 3;
    const size_t col = kb8 + s * 8 + w;
    const unsigned d0 = sdst + (unsigned)(P_AH * 4 + (rr * 9 + w) * 16);
    const unsigned d1 = sdst + (unsigned)(P_AH * 4 + ((rr + 32) * 9 + w) * 16);
    const unsigned d2 = sdst + (unsigned)(P_AL * 4 + (rr * 9 + w) * 16);
    const unsigned d3 = sdst + (unsigned)(P_AL * 4 + ((rr + 32) * 9 + w) * 16);
    const unsigned d4 = sdst + (unsigned)(P_BH * 4 + (rr * 9 + w) * 16);
    const unsigned d5 = sdst + (unsigned)(P_BH * 4 + ((rr + 32) * 9 + w) * 16);
    const unsigned d6 = sdst + (unsigned)(P_BL * 4 + (rr * 9 + w) * 16);
    const unsigned d7 = sdst + (unsigned)(P_BL * 4 + ((rr + 32) * 9 + w) * 16);
    CP_ASYNC16(d0, XH4 + (size_t)(bm + rr)      * 256 + col);
    CP_ASYNC16(d1, XH4 + (size_t)(bm + rr + 32) * 256 + col);
    CP_ASYNC16(d2, XL4 + (size_t)(bm + rr)      * 256 + col);
    CP_ASYNC16(d3, XL4 + (size_t)(bm + rr + 32) * 256 + col);
    CP_ASYNC16(d4, WH4 + (size_t)(bn + rr)      * 256 + col);
    CP_ASYNC16(d5, WH4 + (size_t)(bn + rr + 32) * 256 + col);
    CP_ASYNC16(d6, WL4 + (size_t)(bn + rr)      * 256 + col);
    CP_ASYNC16(d7, WL4 + (size_t)(bn + rr + 32) * 256 + col);
}

// ---------------- kernel 1: cp.async + ldmatrix bf16-split tensor GEMM ----------------
__global__ __launch_bounds__(256) void gemm_mma_kernel() {
    extern __shared__ unsigned smem_dyn[];
    const unsigned sbase = smem_to_u32(smem_dyn);
    const int tid  = threadIdx.x;
    const int lane = tid & 31;
    const int warp = tid >> 5;
    const int wm = warp & 3;
    const int wn = warp >> 2;
    const int bm = blockIdx.y * 64;
    const int bn = blockIdx.x * 64;
    const int kb8 = blockIdx.z * (KSLICE / 8);

    float acc[4][4];
    #pragma unroll
    for (int j = 0; j < 4; j++)
        #pragma unroll
        for (int i = 0; i < 4; i++) acc[j][i] = 0.f;

    const int rr8 = lane & 7;
    const int g1  = (lane >> 3) & 1;
    const int g2  = lane >> 4;
    const unsigned aoffAH = (unsigned)((P_AH + (wm * 16 + rr8 + 8 * g1) * PITCH + 4 * g2) * 4);
    const unsigned aoffAL = aoffAH + (unsigned)((P_AL - P_AH) * 4);
    const unsigned boffH0 = (unsigned)((P_BH + (wn * 32 + (0 + g1) * 8 + rr8) * PITCH + 4 * g2) * 4);
    const unsigned boffH1 = (unsigned)((P_BH + (wn * 32 + (2 + g1) * 8 + rr8) * PITCH + 4 * g2) * 4);
    const unsigned boffL0 = boffH0 + (unsigned)((P_BL - P_BH) * 4);
    const unsigned boffL1 = boffH1 + (unsigned)((P_BL - P_BH) * 4);

    issue_stage(sbase, bm, bn, kb8, 0, tid);
    CP_COMMIT();
    CP_WAIT0();
    __syncthreads();

    #pragma unroll
    for (int s = 0; s < 8; s++) {
        if (s + 1 < 8) {
            issue_stage(sbase + ((s + 1) & 1) * STAGE_B, bm, bn, kb8, s + 1, tid);
            CP_COMMIT();
        }

        const unsigned sb = sbase + (s & 1) * STAGE_B;
        #pragma unroll
        for (int t = 0; t < 4; t++) {
            const unsigned ko = (unsigned)(t * 32);
            unsigned ah[4], al[4], bH0[4], bH1[4], bL0[4], bL1[4];
            LDSM_X4(ah[0], ah[1], ah[2], ah[3], sb + aoffAH + ko);
            LDSM_X4(al[0], al[1], al[2], al[3], sb + aoffAL + ko);
            LDSM_X4(bH0[0], bH0[1], bH0[2], bH0[3], sb + boffH0 + ko);
            LDSM_X4(bH1[0], bH1[1], bH1[2], bH1[3], sb + boffH1 + ko);
            LDSM_X4(bL0[0], bL0[1], bL0[2], bL0[3], sb + boffL0 + ko);
            LDSM_X4(bL1[0], bL1[1], bL1[2], bL1[3], sb + boffL1 + ko);

            unsigned b0[2] = {bH0[0], bH0[2]}, b1[2] = {bH0[1], bH0[3]};
            unsigned b2[2] = {bH1[0], bH1[2]}, b3[2] = {bH1[1], bH1[3]};
            unsigned c0[2] = {bL0[0], bL0[2]}, c1[2] = {bL0[1], bL0[3]};
            unsigned c2[2] = {bL1[0], bL1[2]}, c3[2] = {bL1[1], bL1[3]};

            mma16816(acc[0], ah, b0);
            mma16816(acc[1], ah, b1);
            mma16816(acc[2], ah, b2);
            mma16816(acc[3], ah, b3);
            mma16816(acc[0], ah, c0);
            mma16816(acc[1], ah, c1);
            mma16816(acc[2], ah, c2);
            mma16816(acc[3], ah, c3);
            mma16816(acc[0], al, b0);
            mma16816(acc[1], al, b1);
            mma16816(acc[2], al, b2);
            mma16816(acc[3], al, b3);
        }

        if (s + 1 < 8) {
            CP_WAIT0();
            __syncthreads();
        }
    }

    // epilogue: write split-K partials in GROUP-TRANSPOSED layout
    float* dst = g_hpart[blockIdx.z];
    const int r0 = bm + wm * 16 + (lane >> 2);
    #pragma unroll
    for (int j = 0; j < 4; j++) {
        const int c = bn + wn * 32 + j * 8 + 2 * (lane & 3);
        if (c < OUTCH) {
            const int grp = c >> 2, e = c & 3;   // e in {0,2} -> 8B aligned
            *(float2*)(dst + ((size_t)grp * BSZ + r0) * 4 + e)       = make_float2(acc[j][0], acc[j][1]);
            *(float2*)(dst + ((size_t)grp * BSZ + r0 + 8) * 4 + e)   = make_float2(acc[j][2], acc[j][3]);
        }
    }
}

// ---------------- kernel 2: FUSED split-K sum + BN stats + qkv + attention ----------------
// block c (696 blocks, 640 threads, thread t = row l). All loads coalesced via group layout.
// In-block warp-tree stats (chunk boundary 320 = warp 10) -> A/B; no atomics, deterministic.
__global__ __launch_bounds__(640) void attn_kernel(const float* __restrict__ gamma,
                                                   const float* __restrict__ beta,
                                                   const float* __restrict__ ipw,
                                                   const float* __restrict__ ipb) {
    __shared__ __align__(16) float ks[BSZ];
    __shared__ __align__(16) float vs[BSZ];
    __shared__ float part[20][8];
    __shared__ float ABs[2][8];      // [chunk][0..3]=A, [4..7]=B
    const int c = blockIdx.x, t = threadIdx.x;
    const int n = c >> 2, e = c & 3;
    const int c0 = n * 4;

    // coalesced: sum 4 split-K slices -> h4 ; prior group-transposed -> p4
    float4 h0 = ((const float4*)g_hpart[0])[(size_t)n * BSZ + t];
    float4 h1 = ((const float4*)g_hpart[1])[(size_t)n * BSZ + t];
    float4 h2 = ((const float4*)g_hpart[2])[(size_t)n * BSZ + t];
    float4 h3 = ((const float4*)g_hpart[3])[(size_t)n * BSZ + t];
    float4 p4 = ((const float4*)g_pgrp)[(size_t)n * BSZ + t];
    float hv[4], pv[4];
    hv[0] = (h0.x + h1.x) + (h2.x + h3.x);
    hv[1] = (h0.y + h1.y) + (h2.y + h3.y);
    hv[2] = (h0.z + h1.z) + (h2.z + h3.z);
    hv[3] = (h0.w + h1.w) + (h2.w + h3.w);
    pv[0] = p4.x; pv[1] = p4.y; pv[2] = p4.z; pv[3] = p4.w;

    // in-block ghost-BN stats: warp shuffle reduce (sum, sumsq) x 4 channels
    float r8[8];
    #pragma unroll
    for (int i = 0; i < 4; i++) { r8[i] = hv[i]; r8[4 + i] = hv[i] * hv[i]; }
    #pragma unroll
    for (int o = 16; o; o >>= 1)
        #pragma unroll
        for (int i = 0; i < 8; i++) r8[i] += __shfl_xor_sync(0xFFFFFFFFu, r8[i], o);
    if ((t & 31) == 0)
        #pragma unroll
        for (int i = 0; i < 8; i++) part[t >> 5][i] = r8[i];
    __syncthreads();
    if (t < 8) {
        const int chunk = t >> 2, ch = t & 3;
        float ts = 0.f, tq = 0.f;
        #pragma unroll
        for (int w = 0; w < 10; w++) { ts += part[chunk * 10 + w][ch]; tq += part[chunk * 10 + w][4 + ch]; }
        float mean = ts * (1.f / CHROWS);
        float var  = tq * (1.f / CHROWS) - mean * mean;
        float A = gamma[c0 + ch] * rsqrtf(var + 1e-5f);
        ABs[chunk][ch] = A;
        ABs[chunk][4 + ch] = beta[c0 + ch] - mean * A;
    }
    __syncthreads();

    const int chunk = (t >= CHROWS) ? 1 : 0;
    float hm[4];
    #pragma unroll
    for (int i = 0; i < 4; i++)
        hm[i] = pv[i] * fmaf(hv[i], ABs[chunk][i], ABs[chunk][4 + i]);

    if (e == 0)   // one block per group persists hmul for the epilogue
        *(float4*)(g_hmul + (size_t)t * OUTCH + c0) = make_float4(hm[0], hm[1], hm[2], hm[3]);

    float q = ipb[e], k = ipb[4 + e], v = ipb[8 + e];
    #pragma unroll
    for (int e2 = 0; e2 < 4; e2++) {
        q = fmaf(ipw[e * 4 + e2],       hm[e2], q);
        k = fmaf(ipw[(4 + e) * 4 + e2], pv[e2], k);
        v = fmaf(ipw[(8 + e) * 4 + e2], pv[e2], v);
    }
    ks[t] = k;
    vs[t] = v;
    __syncthreads();

    const float ql = q * LOG2E;
    unsigned long long qq;
    asm("mov.b64 %0, {%1, %1};" : "=l"(qq) : "f"(ql));
    unsigned long long d01 = 0ull, d23 = 0ull, n01 = 0ull, n23 = 0ull;
    const ulonglong2* k2 = (const ulonglong2*)ks;
    const ulonglong2* v2 = (const ulonglong2*)vs;
    #pragma unroll 4
    for (int s = 0; s < BSZ / 4; s++) {
        ulonglong2 kk = k2[s], vv = v2[s];
        unsigned long long p01, p23;
        asm("mul.rn.f32x2 %0, %1, %2;" : "=l"(p01) : "l"(kk.x), "l"(qq));
        asm("mul.rn.f32x2 %0, %1, %2;" : "=l"(p23) : "l"(kk.y), "l"(qq));
        float x0, x1, x2, x3;
        asm("mov.b64 {%0, %1}, %2;" : "=f"(x0), "=f"(x1) : "l"(p01));
        asm("mov.b64 {%0, %1}, %2;" : "=f"(x2), "=f"(x3) : "l"(p23));
        float e0 = ex2(x0), e1 = ex2(x1), e2 = ex2(x2), e3 = ex2(x3);
        unsigned long long e01, e23;
        asm("mov.b64 %0, {%1, %2};" : "=l"(e01) : "f"(e0), "f"(e1));
        asm("mov.b64 %0, {%1, %2};" : "=l"(e23) : "f"(e2), "f"(e3));
        asm("add.rn.f32x2 %0, %0, %1;" : "+l"(d01) : "l"(e01));
        asm("add.rn.f32x2 %0, %0, %1;" : "+l"(d23) : "l"(e23));
        asm("fma.rn.f32x2 %0, %1, %2, %0;" : "+l"(n01) : "l"(e01), "l"(vv.x));
        asm("fma.rn.f32x2 %0, %1, %2, %0;" : "+l"(n23) : "l"(e23), "l"(vv.y));
    }
    float da, db, dc, dd, na, nb, nc, nd;
    asm("mov.b64 {%0, %1}, %2;" : "=f"(da), "=f"(db) : "l"(d01));
    asm("mov.b64 {%0, %1}, %2;" : "=f"(dc), "=f"(dd) : "l"(d23));
    asm("mov.b64 {%0, %1}, %2;" : "=f"(na), "=f"(nb) : "l"(n01));
    asm("mov.b64 {%0, %1}, %2;" : "=f"(nc), "=f"(nd) : "l"(n23));
    g_o[(size_t)t * OUTCH + c] = ((na + nb) + (nc + nd)) / ((da + db) + (dc + dd));
}

// ---------------- kernel 3: out_proj + residual + row softmax ----------------
__global__ __launch_bounds__(256) void epi_kernel(const float* __restrict__ opw,
                                                  const float* __restrict__ opb,
                                                  float* __restrict__ out) {
    __shared__ float orow[OUTCH];
    __shared__ float sh[OUTCH];
    __shared__ float rbuf[8];
    const int l = blockIdx.x, tid = threadIdx.x;

    for (int c = tid; c < OUTCH; c += 256) orow[c] = g_o[(size_t)l * OUTCH + c];
    __syncthreads();

    float lmax = -1e30f;
    for (int c = tid; c < OUTCH; c += 256) {
        int n = c >> 2, e = c & 3;
        float y = opb[e];
        #pragma unroll
        for (int e2 = 0; e2 < 4; e2++) y = fmaf(opw[e * 4 + e2], orow[n * 4 + e2], y);
        float lg = g_hmul[(size_t)l * OUTCH + c] + y;
        sh[c] = lg;
        lmax = fmaxf(lmax, lg);
    }
    #pragma unroll
    for (int o = 16; o; o >>= 1) lmax = fmaxf(lmax, __shfl_xor_sync(0xFFFFFFFFu, lmax, o));
    if ((tid & 31) == 0) rbuf[tid >> 5] = lmax;
    __syncthreads();
    float bmax = rbuf[0];
    #pragma unroll
    for (int i = 1; i < 8; i++) bmax = fmaxf(bmax, rbuf[i]);
    __syncthreads();

    float sum = 0.f;
    for (int c = tid; c < OUTCH; c += 256) {
        float e = ex2((sh[c] - bmax) * LOG2E);
        sh[c] = e;
        sum += e;
    }
    #pragma unroll
    for (int o = 16; o; o >>= 1) sum += __shfl_xor_sync(0xFFFFFFFFu, sum, o);
    if ((tid & 31) == 0) rbuf[tid >> 5] = sum;
    __syncthreads();
    float bsum = 0.f;
    #pragma unroll
    for (int i = 0; i < 8; i++) bsum += rbuf[i];
    float inv = 1.f / bsum;
    for (int c = tid; c < OUTCH; c += 256) out[(size_t)l * OUTCH + c] = sh[c] * inv;
}

// ---------------- launch ----------------
extern "C" void kernel_launch(void* const* d_in, const int* in_sizes, int n_in,
                              void* d_out, int out_size) {
    const float* x     = (const float*)d_in[0];
    const float* prior = (const float*)d_in[1];
    const float* w_lin = (const float*)d_in[2];
    const float* gamma = (const float*)d_in[3];
    const float* beta  = (const float*)d_in[4];
    const float* ipw   = (const float*)d_in[5];
    const float* ipb   = (const float*)d_in[6];
    const float* opw   = (const float*)d_in[7];
    const float* opb   = (const float*)d_in[8];
    float* out = (float*)d_out;

    cudaFuncSetAttribute(gemm_mma_kernel, cudaFuncAttributeMaxDynamicSharedMemorySize, GSMEM);

    prep_kernel<<<(XQ + WQ + PQ + 255) / 256, 256>>>(x, w_lin, prior);
    gemm_mma_kernel<<<dim3(WROWS / 64, BSZ / 64, KSPLIT), 256, GSMEM>>>();
    attn_kernel<<<OUTCH, BSZ>>>(gamma, beta, ipw, ipb);
    epi_kernel<<<BSZ, 256>>>(opw, opb, out);
}